// round 17
// baseline (speedup 1.0000x reference)
#include <cuda_runtime.h>

// Denoise_17669495455833: batched FISTA QP (2 passes x 100 iters, rows of 512 fp32).
// R16: R14 champion body (packed f32x2 pentadiagonal, hoisted w=CE*y, folded boundary
// constants), with __launch_bounds__(64,7): forces <=144 regs so 7 CTAs/SM fit
// (14 warps vs 12). R14 at 166 regs stranded 1.8K regs/SM. No new instructions,
// no memory traffic -- pure occupancy. Spill canary: L1% (R14 baseline 12.4%).

typedef unsigned long long u64;
#define FULL_MASK 0xffffffffu

__device__ u64 g_coefs[100];   // packed (coef, coef) per iteration

__device__ __forceinline__ u64 pk2(float lo, float hi) {
    u64 r;
    asm("mov.b64 %0, {%1,%2};" : "=l"(r) : "r"(__float_as_uint(lo)), "r"(__float_as_uint(hi)));
    return r;
}
__device__ __forceinline__ void upk2(u64 v, float& lo, float& hi) {
    unsigned a, b;
    asm("mov.b64 {%0,%1}, %2;" : "=r"(a), "=r"(b) : "l"(v));
    lo = __uint_as_float(a); hi = __uint_as_float(b);
}
__device__ __forceinline__ u64 fma2(u64 a, u64 b, u64 c) {
    u64 d;
    asm("fma.rn.f32x2 %0, %1, %2, %3;" : "=l"(d) : "l"(a), "l"(b), "l"(c));
    return d;
}
__device__ __forceinline__ u64 add2(u64 a, u64 b) {
    u64 d;
    asm("add.rn.f32x2 %0, %1, %2;" : "=l"(d) : "l"(a), "l"(b));
    return d;
}
__device__ __forceinline__ u64 sub2(u64 a, u64 b) {
    u64 d;
    asm("sub.rn.f32x2 %0, %1, %2;" : "=l"(d) : "l"(a), "l"(b));
    return d;
}
__device__ __forceinline__ u64 mul2(u64 a, u64 b) {
    u64 d;
    asm("mul.rn.f32x2 %0, %1, %2;" : "=l"(d) : "l"(a), "l"(b));
    return d;
}
__device__ __forceinline__ u64 rep2(float f) {
    unsigned u = __float_as_uint(f);
    return ((u64)u << 32) | (u64)u;
}

__global__ void coef_setup_kernel() {
    if (threadIdx.x == 0 && blockIdx.x == 0) {
        float t = 1.0f;
        for (int i = 0; i < 100; ++i) {
            float tn = 0.5f * (1.0f + sqrtf(fmaf(4.0f * t, t, 1.0f)));
            float c  = (t - 1.0f) / tn;
            unsigned u = __float_as_uint(c);
            g_coefs[i] = ((u64)u << 32) | (u64)u;
            t = tn;
        }
    }
}

__global__ void __launch_bounds__(64, 7)
denoise_fista14_kernel(const float* __restrict__ in, float* __restrict__ out, int nrows)
{
    const int gw   = (int)((blockIdx.x * blockDim.x + threadIdx.x) >> 5);  // warp = row pair
    const int lane = (int)(threadIdx.x & 31);
    if (gw * 2 + 1 >= nrows) return;

    const float* rA = in + (size_t)(gw * 2)     * 512 + lane * 16;
    const float* rB = in + (size_t)(gw * 2 + 1) * 512 + lane * 16;

    u64 y[16], w[16], x[16], z[16];
    #pragma unroll
    for (int i = 0; i < 16; i += 4) {
        float4 a4 = *reinterpret_cast<const float4*>(rA + i);
        float4 b4 = *reinterpret_cast<const float4*>(rB + i);
        y[i + 0] = pk2(a4.x, b4.x);
        y[i + 1] = pk2(a4.y, b4.y);
        y[i + 2] = pk2(a4.z, b4.z);
        y[i + 3] = pk2(a4.w, b4.w);
    }

    // LAM = 10, step = 1/322.
    // v = z + CZY*(z-y) + CDT*DtD(z),  CZY = -2/322, CDT = -20/322. Precombined:
    const float STEPf = 1.0f / 322.0f;
    const float CZYf  = -2.0f * STEPf;
    const float CDTf  = -2.0f * 10.0f * STEPf;
    const float CAf   = 1.0f + CZYf + 6.0f * CDTf;    // z_j
    const float CBf   = -4.0f * CDTf;                 // z_{j+-1}

    const bool first = (lane == 0);
    const bool last  = (lane == 31);

    // boundary corrections folded into per-lane, per-k effective constants.
    const float q1 = -5.0f * CDTf, q2 = 2.0f * CDTf, q3 = -1.0f * CDTf;
    const u64 CA    = rep2(CAf);
    const u64 CAk0  = rep2(CAf + (first ? q1 : 0.0f));
    const u64 CAk1  = rep2(CAf + (first ? q3 : 0.0f));
    const u64 CAk14 = rep2(CAf + (last  ? q3 : 0.0f));
    const u64 CAk15 = rep2(CAf + (last  ? q1 : 0.0f));
    const u64 CB    = rep2(CBf);
    const u64 CBk0  = rep2(CBf + (first ? q2 : 0.0f));   // s1 = zR1 only (p1 masked 0)
    const u64 CBk15 = rep2(CBf + (last  ? q2 : 0.0f));   // s1 = p1 only (zR1 masked 0)
    const u64 CC    = rep2(CDTf);                        // z_{j+-2}
    const u64 Q2F   = first ? rep2(q2) : 0ULL;           // extra fma at k=1 (on p1=old z0)
    const u64 Q2L   = last  ? rep2(q2) : 0ULL;           // extra fma at k=14 (on old z15)
    const u64 CE    = rep2(-CZYf);                       // y_j (hoisted: w = CE*y per pass)

    #pragma unroll 1
    for (int pass = 0; pass < 2; ++pass) {
        #pragma unroll
        for (int k = 0; k < 16; ++k) {
            x[k] = y[k]; z[k] = y[k];          // x0 = proj(y) = y
            w[k] = mul2(y[k], CE);             // hoisted data term (constant per pass)
        }

        #pragma unroll 1
        for (int it = 0; it < 100; ++it) {
            const u64 coefP = g_coefs[it];

            // neighbor pairs (previous iterate); out-of-range -> 0 via SEL (no branch)
            u64 zm2 = __shfl_up_sync  (FULL_MASK, z[14], 1);
            u64 zm1 = __shfl_up_sync  (FULL_MASK, z[15], 1);
            u64 zp1 = __shfl_down_sync(FULL_MASK, z[0],  1);
            u64 zp2 = __shfl_down_sync(FULL_MASK, z[1],  1);
            zm2 = first ? 0ULL : zm2;
            zm1 = first ? 0ULL : zm1;
            zp1 = last  ? 0ULL : zp1;
            zp2 = last  ? 0ULL : zp2;

            // rotating window of OLD z values (z[] is overwritten in place)
            u64 p2 = zm2, p1 = zm1;

            #pragma unroll
            for (int k = 0; k < 16; ++k) {
                u64 zc  = z[k];                                 // old z_j
                u64 zR1 = (k <= 14) ? z[k + 1] : zp1;           // old z_{j+1}
                u64 zR2 = (k <= 13) ? z[k + 2] : ((k == 14) ? zp1 : zp2);  // old z_{j+2}

                const u64 CAk = (k == 0) ? CAk0 : (k == 1) ? CAk1
                              : (k == 14) ? CAk14 : (k == 15) ? CAk15 : CA;
                const u64 CBk = (k == 0) ? CBk0 : (k == 15) ? CBk15 : CB;

                u64 s1 = add2(p1, zR1);
                u64 s2 = add2(p2, zR2);
                u64 v  = fma2(zc, CAk, w[k]);
                v = fma2(s1, CBk, v);
                v = fma2(s2, CC, v);
                if (k == 1)  v = fma2(p1,  Q2F, v);   // unconditional, lane-masked const
                if (k == 14) v = fma2(zR1, Q2L, v);   // zR1 here = old z[15]

                // x_new = clip(v, 0, y)  (scalar FMNMX -> alu pipe)
                float vlo, vhi, ylo, yhi;
                upk2(v, vlo, vhi);
                upk2(y[k], ylo, yhi);
                u64 xn = pk2(fminf(fmaxf(vlo, 0.0f), ylo),
                             fminf(fmaxf(vhi, 0.0f), yhi));

                // z_new = x_new + coef*(x_new - x)
                u64 dx = sub2(xn, x[k]);
                z[k] = fma2(dx, coefP, xn);
                x[k] = xn;

                p2 = p1; p1 = zc;
            }
        }

        if (pass == 0) {
            #pragma unroll
            for (int k = 0; k < 16; ++k) y[k] = x[k];   // pass 2: y = pass-1 output
        }
    }

    float* oA = out + (size_t)(gw * 2)     * 512 + lane * 16;
    float* oB = out + (size_t)(gw * 2 + 1) * 512 + lane * 16;
    #pragma unroll
    for (int i = 0; i < 16; i += 4) {
        float4 a4, b4;
        upk2(x[i + 0], a4.x, b4.x);
        upk2(x[i + 1], a4.y, b4.y);
        upk2(x[i + 2], a4.z, b4.z);
        upk2(x[i + 3], a4.w, b4.w);
        *reinterpret_cast<float4*>(oA + i) = a4;
        *reinterpret_cast<float4*>(oB + i) = b4;
    }
}

extern "C" void kernel_launch(void* const* d_in, const int* in_sizes, int n_in,
                              void* d_out, int out_size)
{
    const float* in  = (const float*)d_in[0];
    float*       out = (float*)d_out;
    const int nrows  = in_sizes[0] / 512;            // 16384 rows
    coef_setup_kernel<<<1, 32>>>();
    const int warps  = nrows / 2;                    // 2 rows per warp
    const int blocks = (warps + 1) / 2;              // 2 warps per 64-thread block
    denoise_fista14_kernel<<<blocks, 64>>>(in, out, nrows);
}